// round 11
// baseline (speedup 1.0000x reference)
#include <cuda_runtime.h>

// ---------------------------------------------------------------------------
// Problem constants
// ---------------------------------------------------------------------------
#define HH   8
#define DD   128
#define KDD  16
#define EE   128
#define BB   16
#define GG   501
#define NPP  250
#define NTOK (BB*GG)      // 8016
#define NHALF (BB*NPP)    // 4000
#define SCALE2 0.3606737602222409f   // (1/sqrt(16)) * log2(e)

typedef unsigned long long ull;

// ---------------------------------------------------------------------------
// Scratch
// ---------------------------------------------------------------------------
__device__ float g_qT[DD*NTOK];            // transposed input: [d][token]
__device__ float g_Q[HH*NTOK*KDD];
__device__ float g_K[HH*NTOK*KDD];
__device__ float g_V[HH*NTOK*KDD];
// [0]=W1(pick single) [1]=W2(pick vs K_pick) [2]=W3(pick vs K_del)
// [3]=W4(del single)  [4]=W5(del vs K_del)   [5]=W6(del vs K_pick)
__device__ float g_EQ[6][HH*NHALF*KDD];
__device__ float g_pacc[4][HH*NTOK*KDD];   // partial sum(w*V) per key-quarter
__device__ float g_pl[4][HH*NTOK];         // partial sum(w)   per key-quarter

struct WArgs { const float* w[9]; };

// ---------------------------------------------------------------------------
// Packed fp32x2 helpers
// ---------------------------------------------------------------------------
__device__ __forceinline__ ull mul2(ull a, ull b) {
    ull r; asm("mul.rn.f32x2 %0,%1,%2;" : "=l"(r) : "l"(a), "l"(b)); return r;
}
__device__ __forceinline__ void fma2(ull& d, ull a, ull b) {
    asm("fma.rn.f32x2 %0,%1,%2,%0;" : "+l"(d) : "l"(a), "l"(b));
}
__device__ __forceinline__ ull add2(ull a, ull b) {
    ull r; asm("add.rn.f32x2 %0,%1,%2;" : "=l"(r) : "l"(a), "l"(b)); return r;
}
__device__ __forceinline__ ull pk2(float lo, float hi) {
    ull r; asm("mov.b64 %0,{%1,%2};" : "=l"(r) : "f"(lo), "f"(hi)); return r;
}
__device__ __forceinline__ float2 up2(ull a) {
    float lo, hi; asm("mov.b64 {%0,%1},%2;" : "=f"(lo), "=f"(hi) : "l"(a));
    return make_float2(lo, hi);
}
__device__ __forceinline__ float ex2(float x) {
    float r; asm("ex2.approx.f32 %0, %1;" : "=f"(r) : "f"(x)); return r;
}

// ---------------------------------------------------------------------------
// Kernel 0: transpose q [token][d] -> g_qT [d][token]. 32x32 tiles.
// ---------------------------------------------------------------------------
__global__ void transpose_kernel(const float* __restrict__ q) {
    __shared__ float s[32][33];
    const int t0 = blockIdx.x * 32;
    const int d0 = blockIdx.y * 32;
    const int x = threadIdx.x, y = threadIdx.y;   // block (32,8)
#pragma unroll
    for (int j = 0; j < 32; j += 8) {
        int t = t0 + y + j;
        s[y+j][x] = (t < NTOK) ? q[(size_t)t*DD + d0 + x] : 0.f;
    }
    __syncthreads();
#pragma unroll
    for (int j = 0; j < 32; j += 8) {
        int t = t0 + x;
        if (t < NTOK) g_qT[(size_t)(d0 + y + j)*NTOK + t] = s[x][y+j];
    }
}

// ---------------------------------------------------------------------------
// Kernel 1: projections as folded GEMMs, d-major q tile (row-pairs packed
// directly by LDS.128 — no q pk2).
// Tile 128 rows x 64 cols, 256 threads, thread = 8 rows (4 pairs) x 4 cols.
// grid (381, 2 col-halves): full jobs 63 tiles, half jobs 32 tiles.
// ---------------------------------------------------------------------------
__global__ void __launch_bounds__(256, 2) proj_kernel(WArgs a) {
    extern __shared__ float sm[];
    float* qsT = sm;              // 128 d x 128 rows (stride 128)
    float* ws  = sm + 128*128;    // 128 d x 64 cols

    int bx = blockIdx.x;
    const int ch = blockIdx.y;    // column half (0/1)
    int job, tile;
    if (bx < 189) { job = bx / 63; tile = bx % 63; }
    else          { bx -= 189; job = 3 + bx / 32; tile = bx % 32; }

    const bool full = (job < 3);
    const int nrows = full ? NTOK : NHALF;
    const int r0 = tile * 128;
    const int tid = threadIdx.x;

    // ---- weight tile (float4): ws[d*64+col] = W[h][d][k], col=(h*16+k)-ch*64
    {
        const float4* W4 = (const float4*)a.w[job];
        float4* ws4 = (float4*)ws;
        for (int i = tid; i < DD*16; i += 256) {
            int d = i >> 4, c4 = i & 15;
            int gc4 = ch*16 + c4;
            ws4[i] = W4[(gc4 >> 2)*(DD*4) + d*4 + (gc4 & 3)];
        }
    }

    // ---- q tile, d-major ----
    if (full) {
        // rows are tokens directly; NTOK % 4 == 0 -> float4 fully in/out
        float4* q4 = (float4*)qsT;
        for (int i = tid; i < 128*32; i += 256) {
            int d = i >> 5, r4 = i & 31;
            int t = r0 + r4*4;
            float4 v = make_float4(0.f, 0.f, 0.f, 0.f);
            if (t < NTOK) v = *(const float4*)(g_qT + (size_t)d*NTOK + t);
            q4[d*32 + r4] = v;
        }
    } else {
        const int off = (job < 6) ? 1 : (NPP + 1);
        for (int i = tid; i < 128*128; i += 256) {
            int d = i >> 7, r = i & 127;
            int rt = r0 + r;
            float v = 0.f;
            if (rt < NHALF) {
                int b = rt / NPP, p = rt % NPP;
                v = g_qT[(size_t)d*NTOK + b*GG + off + p];
            }
            qsT[d*128 + r] = v;
        }
    }
    __syncthreads();

    const int cg = tid & 15;      // cols cg*4 .. +3 (within 64-col half)
    const int rg = tid >> 4;      // rows rg*8 .. +7 (4 packed pairs)

    ull acc[4][4];
#pragma unroll
    for (int p = 0; p < 4; p++)
#pragma unroll
        for (int c = 0; c < 4; c++) acc[p][c] = 0ull;

#pragma unroll 4
    for (int d = 0; d < DD; d++) {
        const float* qb = qsT + d*128 + rg*8;
        ulonglong2 qa = *(const ulonglong2*)(qb);       // pairs (r0,r1),(r2,r3)
        ulonglong2 qc = *(const ulonglong2*)(qb + 4);   // pairs (r4,r5),(r6,r7)
        float4 w = *(const float4*)(ws + d*64 + cg*4);
        ull w0 = pk2(w.x, w.x), w1 = pk2(w.y, w.y);
        ull w2 = pk2(w.z, w.z), w3 = pk2(w.w, w.w);
        fma2(acc[0][0], qa.x, w0); fma2(acc[0][1], qa.x, w1);
        fma2(acc[0][2], qa.x, w2); fma2(acc[0][3], qa.x, w3);
        fma2(acc[1][0], qa.y, w0); fma2(acc[1][1], qa.y, w1);
        fma2(acc[1][2], qa.y, w2); fma2(acc[1][3], qa.y, w3);
        fma2(acc[2][0], qc.x, w0); fma2(acc[2][1], qc.x, w1);
        fma2(acc[2][2], qc.x, w2); fma2(acc[2][3], qc.x, w3);
        fma2(acc[3][0], qc.y, w0); fma2(acc[3][1], qc.y, w1);
        fma2(acc[3][2], qc.y, w2); fma2(acc[3][3], qc.y, w3);
    }

    float* outp;
    if      (job == 0) outp = g_Q;
    else if (job == 1) outp = g_K;
    else if (job == 2) outp = g_V;
    else               outp = g_EQ[job-3];

    const int gcol0 = ch*64 + cg*4;
    const int h  = gcol0 >> 4;
    const int k0 = gcol0 & 15;
#pragma unroll
    for (int p = 0; p < 4; p++) {
        float2 c0 = up2(acc[p][0]), c1 = up2(acc[p][1]);
        float2 c2 = up2(acc[p][2]), c3 = up2(acc[p][3]);
        int rlo = r0 + rg*8 + 2*p;
        if (rlo < nrows) {
            float* o = outp + ((size_t)h*nrows + rlo)*KDD + k0;
            *(float4*)o = make_float4(c0.x, c1.x, c2.x, c3.x);
        }
        if (rlo + 1 < nrows) {
            float* o = outp + ((size_t)h*nrows + rlo + 1)*KDD + k0;
            *(float4*)o = make_float4(c0.y, c1.y, c2.y, c3.y);
        }
    }
}

// ---------------------------------------------------------------------------
// Attention helpers. K/V row = 16 floats = 4 ulonglong2.
// ---------------------------------------------------------------------------
__device__ __forceinline__ float dotp(const ull* qp,
        ulonglong2 ka, ulonglong2 kb, ulonglong2 kc, ulonglong2 kd) {
    ull p0 = mul2(qp[0], ka.x);
    ull p1 = mul2(qp[1], ka.y);
    fma2(p0, qp[2], kb.x); fma2(p1, qp[3], kb.y);
    fma2(p0, qp[4], kc.x); fma2(p1, qp[5], kc.y);
    fma2(p0, qp[6], kd.x); fma2(p1, qp[7], kd.y);
    float2 s = up2(add2(p0, p1));
    return s.x + s.y;
}

__device__ __forceinline__ void accum(float w, ull* acc, float& l,
        ulonglong2 va, ulonglong2 vb, ulonglong2 vc, ulonglong2 vd) {
    l += w;
    ull wp = pk2(w, w);
    fma2(acc[0], wp, va.x); fma2(acc[1], wp, va.y);
    fma2(acc[2], wp, vb.x); fma2(acc[3], wp, vb.y);
    fma2(acc[4], wp, vc.x); fma2(acc[5], wp, vc.y);
    fma2(acc[6], wp, vd.x); fma2(acc[7], wp, vd.y);
}

__device__ __forceinline__ void attn_key2(const ulonglong2* KsU, const ulonglong2* VsU,
        int j,
        const ull* qp0, bool a0, float& l0, ull* acc0,
        const ull* qp1, bool a1, float& l1, ull* acc1) {
    ulonglong2 ka = KsU[j*4+0], kb = KsU[j*4+1], kc = KsU[j*4+2], kd = KsU[j*4+3];
    float s0 = dotp(qp0, ka, kb, kc, kd);
    float s1 = dotp(qp1, ka, kb, kc, kd);
    float w0 = a0 ? ex2(s0) : 0.f;
    float w1 = a1 ? ex2(s1) : 0.f;
    ulonglong2 va = VsU[j*4+0], vb = VsU[j*4+1], vc = VsU[j*4+2], vd = VsU[j*4+3];
    accum(w0, acc0, l0, va, vb, vc, vd);
    accum(w1, acc1, l1, va, vb, vc, vd);
}

__device__ __forceinline__ void loadq(const float* src, ull* qp) {
    const float4* s4 = (const float4*)src;
#pragma unroll
    for (int t = 0; t < 4; t++) {
        float4 v = s4[t];
        qp[2*t]   = pk2(v.x*SCALE2, v.y*SCALE2);
        qp[2*t+1] = pk2(v.z*SCALE2, v.w*SCALE2);
    }
}

// ---------------------------------------------------------------------------
// Kernel 2: attention split over key QUARTERS.
// grid (HB=128, 2 qchunks, 4 key-quarters), block 128, 2 queries/thread.
// Quarters: z=0 keys [0,126), z=1 [126,251), z=2 [251,376), z=3 [376,501).
// ---------------------------------------------------------------------------
__global__ void __launch_bounds__(128, 4) attn_kernel() {
    extern __shared__ float sm[];
    const ulonglong2* KsU = (const ulonglong2*)sm;        // 126 rows * 4
    const ulonglong2* VsU = KsU + 126*4;

    const int hb  = blockIdx.x;
    const int tid = threadIdx.x;
    const int z   = blockIdx.z;
    const int kstart = (z==0) ? 0 : (z==1) ? 126 : (z==2) ? 251 : 376;
    const int nk     = (z==0) ? 126 : 125;

    {
        const float4* K4 = (const float4*)(g_K + ((size_t)hb*GG + kstart)*KDD);
        const float4* V4 = (const float4*)(g_V + ((size_t)hb*GG + kstart)*KDD);
        float4* Ks4 = (float4*)sm;
        float4* Vs4 = Ks4 + 126*4;
        for (int i = tid; i < nk*4; i += 128) {
            Ks4[i] = K4[i];
            Vs4[i] = V4[i];
        }
    }
    __syncthreads();

    const int base = blockIdx.y * 256;
    const int n0 = base + tid;
    const int n1 = base + 128 + tid;
    const bool v0 = (n0 < GG);
    const bool v1 = (n1 < GG);
    const int nn0 = v0 ? n0 : 0;
    const int nn1 = v1 ? n1 : 0;

    ull qp0[8], qp1[8], acc0[8], acc1[8];
    float l0 = 0.f, l1 = 0.f;
#pragma unroll
    for (int k = 0; k < 8; k++) { acc0[k] = 0ull; acc1[k] = 0ull; }
    loadq(g_Q + ((size_t)hb*GG + nn0)*KDD, qp0);
    loadq(g_Q + ((size_t)hb*GG + nn1)*KDD, qp1);

    // ---- base: this quarter's keys with Q ----
    for (int j = 0; j < nk; j++)
        attn_key2(KsU, VsU, j, qp0, true, l0, acc0, qp1, true, l1, acc1);

    const bool pk0 = (n0 >= 1) && (n0 <= NPP);
    const bool dl0 = (n0 >= NPP+1) && (n0 < GG);
    const bool ex0 = pk0 || dl0;
    const int  p0  = pk0 ? (n0-1) : (n0-NPP-1);
    const bool pk1 = (n1 >= 1) && (n1 <= NPP);
    const bool dl1 = (n1 >= NPP+1) && (n1 < GG);
    const bool ex1 = pk1 || dl1;
    const int  p1  = pk1 ? (n1-1) : (n1-NPP-1);

    // ---- extras over this quarter's keys ----
    {
        const float* e0src = (z < 2) ? (pk0 ? g_EQ[1] : g_EQ[5]) : (pk0 ? g_EQ[2] : g_EQ[4]);
        const float* e1src = (z < 2) ? (pk1 ? g_EQ[1] : g_EQ[5]) : (pk1 ? g_EQ[2] : g_EQ[4]);
        if (ex0) loadq(e0src + ((size_t)hb*NPP + p0)*KDD, qp0);
        if (ex1) loadq(e1src + ((size_t)hb*NPP + p1)*KDD, qp1);
        const int st = (z == 0) ? 1 : 0;     // skip global key 0 in quarter 0
        for (int j = st; j < st + 125; j++)
            attn_key2(KsU, VsU, j, qp0, ex0, l0, acc0, qp1, ex1, l1, acc1);
    }

    // ---- paired single extras (assigned by key location) ----
    {
        // z<2: delivery query, key 1+p, q=EQ3;  z>=2: pick query, key 251+p, q=EQ0
        const bool c0 = (z < 2) ? dl0 : pk0;
        const bool c1 = (z < 2) ? dl1 : pk1;
        const float* psrc = (z < 2) ? g_EQ[3] : g_EQ[0];
        if (c0) {
            int keyg = ((z < 2) ? 1 : 251) + p0;
            int loc = keyg - kstart;
            if (loc >= 0 && loc < nk) {
                loadq(psrc + ((size_t)hb*NPP + p0)*KDD, qp0);
                float w = ex2(dotp(qp0, KsU[loc*4+0], KsU[loc*4+1], KsU[loc*4+2], KsU[loc*4+3]));
                accum(w, acc0, l0, VsU[loc*4+0], VsU[loc*4+1], VsU[loc*4+2], VsU[loc*4+3]);
            }
        }
        if (c1) {
            int keyg = ((z < 2) ? 1 : 251) + p1;
            int loc = keyg - kstart;
            if (loc >= 0 && loc < nk) {
                loadq(psrc + ((size_t)hb*NPP + p1)*KDD, qp1);
                float w = ex2(dotp(qp1, KsU[loc*4+0], KsU[loc*4+1], KsU[loc*4+2], KsU[loc*4+3]));
                accum(w, acc1, l1, VsU[loc*4+0], VsU[loc*4+1], VsU[loc*4+2], VsU[loc*4+3]);
            }
        }
    }

    // ---- store raw partials ----
    if (v0) {
        float4* o = (float4*)(g_pacc[z] + ((size_t)hb*GG + n0)*KDD);
#pragma unroll
        for (int t = 0; t < 4; t++) {
            float2 a0 = up2(acc0[2*t]);
            float2 a1 = up2(acc0[2*t+1]);
            o[t] = make_float4(a0.x, a0.y, a1.x, a1.y);
        }
        g_pl[z][(size_t)hb*GG + n0] = l0;
    }
    if (v1) {
        float4* o = (float4*)(g_pacc[z] + ((size_t)hb*GG + n1)*KDD);
#pragma unroll
        for (int t = 0; t < 4; t++) {
            float2 a0 = up2(acc1[2*t]);
            float2 a1 = up2(acc1[2*t+1]);
            o[t] = make_float4(a0.x, a0.y, a1.x, a1.y);
        }
        g_pl[z][(size_t)hb*GG + n1] = l1;
    }
}

// ---------------------------------------------------------------------------
// Kernel 3: combine 4 partials + normalize + output projection (packed).
// grid (251 token-tiles of 32, 2 E-halves), block 128.
// ---------------------------------------------------------------------------
__global__ void __launch_bounds__(128, 4) out_kernel(const float* __restrict__ Wout,
                                                     float* __restrict__ out) {
    extern __shared__ float sm[];
    float* hs   = sm;                    // 32 * 132
    float* ws   = sm + 32*132;           // 128 * 64 (E half)
    float* sinv = ws + 128*64;           // 32 * 8

    const int tid = threadIdx.x;
    const int t0  = blockIdx.x * 32;
    const int ech = blockIdx.y;          // E half (0/1)

    // ws (float4): slice cols [ech*64, ech*64+64)
    {
        const float4* W4 = (const float4*)Wout;
        float4* ws4 = (float4*)ws;
        for (int i = tid; i < 128*16; i += 128) {
            int hk = i >> 4, c4 = i & 15;
            ws4[i] = W4[hk*32 + ech*16 + c4];
        }
    }
    // sinv: per (token, head) reciprocal of total l
    for (int i = tid; i < 32*8; i += 128) {
        int t = i >> 3, h = i & 7;
        int tt = t0 + t;
        float l = 1.f;
        if (tt < NTOK) {
            size_t idx = (size_t)h*NTOK + tt;
            l = (g_pl[0][idx] + g_pl[1][idx]) + (g_pl[2][idx] + g_pl[3][idx]);
        }
        sinv[i] = 1.0f / l;
    }
    __syncthreads();

    // hs: combine 4 partials, normalize
    for (int i = tid; i < 32*8*4; i += 128) {      // (t, h, k4)
        int t = i >> 5, h = (i >> 2) & 7, k4 = i & 3;
        int tt = t0 + t;
        float4 v = make_float4(0.f, 0.f, 0.f, 0.f);
        if (tt < NTOK) {
            size_t idx4 = (((size_t)h*NTOK + tt)*KDD >> 2) + k4;
            float4 a = ((const float4*)g_pacc[0])[idx4];
            float4 b = ((const float4*)g_pacc[1])[idx4];
            float4 c = ((const float4*)g_pacc[2])[idx4];
            float4 d = ((const float4*)g_pacc[3])[idx4];
            float s = sinv[t*8 + h];
            v = make_float4(((a.x+b.x)+(c.x+d.x))*s, ((a.y+b.y)+(c.y+d.y))*s,
                            ((a.z+b.z)+(c.z+d.z))*s, ((a.w+b.w)+(c.w+d.w))*s);
        }
        *(float4*)(hs + t*132 + h*16 + k4*4) = v;
    }
    __syncthreads();

    const int eg = tid & 7;          // cols eg*8 .. +7 within the 64-col half
    const int tg = tid >> 3;         // 16 groups of 2 tokens
    const ulonglong2* wsU = (const ulonglong2*)ws;   // 16 per hk-row

    ull acc[2][4];
#pragma unroll
    for (int ti = 0; ti < 2; ti++)
#pragma unroll
        for (int c = 0; c < 4; c++) acc[ti][c] = 0ull;

#pragma unroll 4
    for (int hk = 0; hk < 128; hk++) {
        ulonglong2 wa = wsU[hk*16 + eg*2];
        ulonglong2 wb = wsU[hk*16 + eg*2 + 1];
        ull hb[2];
#pragma unroll
        for (int ti = 0; ti < 2; ti++) {
            float hv = hs[(tg*2 + ti)*132 + hk];
            hb[ti] = pk2(hv, hv);
        }
#pragma unroll
        for (int ti = 0; ti < 2; ti++) {
            fma2(acc[ti][0], hb[ti], wa.x);
            fma2(acc[ti][1], hb[ti], wa.y);
            fma2(acc[ti][2], hb[ti], wb.x);
            fma2(acc[ti][3], hb[ti], wb.y);
        }
    }

#pragma unroll
    for (int ti = 0; ti < 2; ti++) {
        int tt = t0 + tg*2 + ti;
        if (tt < NTOK) {
            float2 a0 = up2(acc[ti][0]), a1 = up2(acc[ti][1]);
            float2 a2 = up2(acc[ti][2]), a3 = up2(acc[ti][3]);
            float* o = out + (size_t)tt*EE + ech*64 + eg*8;
            *(float4*)(o)     = make_float4(a0.x, a0.y, a1.x, a1.y);
            *(float4*)(o + 4) = make_float4(a2.x, a2.y, a3.x, a3.y);
        }
    }
}

// ---------------------------------------------------------------------------
extern "C" void kernel_launch(void* const* d_in, const int* in_sizes, int n_in,
                              void* d_out, int out_size) {
    const float* q = (const float*)d_in[0];
    WArgs wa;
    for (int i = 0; i < 9; i++) wa.w[i] = (const float*)d_in[1 + i];
    const float* Wout = (const float*)d_in[10];
    float* out = (float*)d_out;

    const int projSmem = (128*128 + 128*64) * sizeof(float);     // 98304 B
    const int attnSmem = 126*KDD*2*sizeof(float);                // 16128 B
    const int outSmem  = (32*132 + 128*64 + 32*8) * sizeof(float);
    cudaFuncSetAttribute(proj_kernel, cudaFuncAttributeMaxDynamicSharedMemorySize, projSmem);
    cudaFuncSetAttribute(attn_kernel, cudaFuncAttributeMaxDynamicSharedMemorySize, attnSmem);
    cudaFuncSetAttribute(out_kernel,  cudaFuncAttributeMaxDynamicSharedMemorySize, outSmem);

    transpose_kernel<<<dim3((NTOK + 31)/32, 4), dim3(32, 8)>>>(q);
    proj_kernel<<<dim3(381, 2), 256, projSmem>>>(wa);
    attn_kernel<<<dim3(HH*BB, 2, 4), 128, attnSmem>>>();
    out_kernel<<<dim3((NTOK + 31)/32, 2), 128, outSmem>>>(Wout, out);
}

// round 12
// speedup vs baseline: 1.0542x; 1.0542x over previous
#include <cuda_runtime.h>

// ---------------------------------------------------------------------------
// Problem constants
// ---------------------------------------------------------------------------
#define HH   8
#define DD   128
#define KDD  16
#define EE   128
#define BB   16
#define GG   501
#define NPP  250
#define NTOK (BB*GG)      // 8016
#define NHALF (BB*NPP)    // 4000
#define SCALE2 0.3606737602222409f   // (1/sqrt(16)) * log2(e)

typedef unsigned long long ull;

// ---------------------------------------------------------------------------
// Scratch
// ---------------------------------------------------------------------------
__device__ float g_qT[DD*NTOK];            // transposed input: [d][token]
__device__ float g_Q[HH*NTOK*KDD];
__device__ float g_K[HH*NTOK*KDD];
__device__ float g_V[HH*NTOK*KDD];
// [0]=W1(pick single) [1]=W2(pick vs K_pick) [2]=W3(pick vs K_del)
// [3]=W4(del single)  [4]=W5(del vs K_del)   [5]=W6(del vs K_pick)
__device__ float g_EQ[6][HH*NHALF*KDD];
__device__ float g_pacc[4][HH*NTOK*KDD];   // partial sum(w*V) per key-quarter
__device__ float g_pl[4][HH*NTOK];         // partial sum(w)   per key-quarter

struct WArgs { const float* w[9]; };

// ---------------------------------------------------------------------------
// Packed fp32x2 helpers
// ---------------------------------------------------------------------------
__device__ __forceinline__ ull mul2(ull a, ull b) {
    ull r; asm("mul.rn.f32x2 %0,%1,%2;" : "=l"(r) : "l"(a), "l"(b)); return r;
}
__device__ __forceinline__ void fma2(ull& d, ull a, ull b) {
    asm("fma.rn.f32x2 %0,%1,%2,%0;" : "+l"(d) : "l"(a), "l"(b));
}
__device__ __forceinline__ ull add2(ull a, ull b) {
    ull r; asm("add.rn.f32x2 %0,%1,%2;" : "=l"(r) : "l"(a), "l"(b)); return r;
}
__device__ __forceinline__ ull pk2(float lo, float hi) {
    ull r; asm("mov.b64 %0,{%1,%2};" : "=l"(r) : "f"(lo), "f"(hi)); return r;
}
__device__ __forceinline__ float2 up2(ull a) {
    float lo, hi; asm("mov.b64 {%0,%1},%2;" : "=f"(lo), "=f"(hi) : "l"(a));
    return make_float2(lo, hi);
}
__device__ __forceinline__ float ex2(float x) {
    float r; asm("ex2.approx.f32 %0, %1;" : "=f"(r) : "f"(x)); return r;
}

// ---------------------------------------------------------------------------
// Kernel 0: transpose q [token][d] -> g_qT [d][token]. 32x32 tiles.
// ---------------------------------------------------------------------------
__global__ void transpose_kernel(const float* __restrict__ q) {
    __shared__ float s[32][33];
    const int t0 = blockIdx.x * 32;
    const int d0 = blockIdx.y * 32;
    const int x = threadIdx.x, y = threadIdx.y;   // block (32,8)
#pragma unroll
    for (int j = 0; j < 32; j += 8) {
        int t = t0 + y + j;
        s[y+j][x] = (t < NTOK) ? q[(size_t)t*DD + d0 + x] : 0.f;
    }
    __syncthreads();
#pragma unroll
    for (int j = 0; j < 32; j += 8) {
        int t = t0 + x;
        if (t < NTOK) g_qT[(size_t)(d0 + y + j)*NTOK + t] = s[x][y+j];
    }
}

// ---------------------------------------------------------------------------
// Kernel 1: projections as folded GEMMs, d-major q tile.
// Tile 128 rows x 64 cols, 256 threads, thread = 8 rows (4 pairs) x 4 cols.
// ---------------------------------------------------------------------------
__global__ void __launch_bounds__(256, 2) proj_kernel(WArgs a) {
    extern __shared__ float sm[];
    float* qsT = sm;              // 128 d x 128 rows
    float* ws  = sm + 128*128;    // 128 d x 64 cols

    int bx = blockIdx.x;
    const int ch = blockIdx.y;    // column half (0/1)
    int job, tile;
    if (bx < 189) { job = bx / 63; tile = bx % 63; }
    else          { bx -= 189; job = 3 + bx / 32; tile = bx % 32; }

    const bool full = (job < 3);
    const int nrows = full ? NTOK : NHALF;
    const int r0 = tile * 128;
    const int tid = threadIdx.x;

    {
        const float4* W4 = (const float4*)a.w[job];
        float4* ws4 = (float4*)ws;
        for (int i = tid; i < DD*16; i += 256) {
            int d = i >> 4, c4 = i & 15;
            int gc4 = ch*16 + c4;
            ws4[i] = W4[(gc4 >> 2)*(DD*4) + d*4 + (gc4 & 3)];
        }
    }

    if (full) {
        float4* q4 = (float4*)qsT;
        for (int i = tid; i < 128*32; i += 256) {
            int d = i >> 5, r4 = i & 31;
            int t = r0 + r4*4;
            float4 v = make_float4(0.f, 0.f, 0.f, 0.f);
            if (t < NTOK) v = *(const float4*)(g_qT + (size_t)d*NTOK + t);
            q4[d*32 + r4] = v;
        }
    } else {
        const int off = (job < 6) ? 1 : (NPP + 1);
        for (int i = tid; i < 128*128; i += 256) {
            int d = i >> 7, r = i & 127;
            int rt = r0 + r;
            float v = 0.f;
            if (rt < NHALF) {
                int b = rt / NPP, p = rt % NPP;
                v = g_qT[(size_t)d*NTOK + b*GG + off + p];
            }
            qsT[d*128 + r] = v;
        }
    }
    __syncthreads();

    const int cg = tid & 15;
    const int rg = tid >> 4;

    ull acc[4][4];
#pragma unroll
    for (int p = 0; p < 4; p++)
#pragma unroll
        for (int c = 0; c < 4; c++) acc[p][c] = 0ull;

#pragma unroll 4
    for (int d = 0; d < DD; d++) {
        const float* qb = qsT + d*128 + rg*8;
        ulonglong2 qa = *(const ulonglong2*)(qb);
        ulonglong2 qc = *(const ulonglong2*)(qb + 4);
        float4 w = *(const float4*)(ws + d*64 + cg*4);
        ull w0 = pk2(w.x, w.x), w1 = pk2(w.y, w.y);
        ull w2 = pk2(w.z, w.z), w3 = pk2(w.w, w.w);
        fma2(acc[0][0], qa.x, w0); fma2(acc[0][1], qa.x, w1);
        fma2(acc[0][2], qa.x, w2); fma2(acc[0][3], qa.x, w3);
        fma2(acc[1][0], qa.y, w0); fma2(acc[1][1], qa.y, w1);
        fma2(acc[1][2], qa.y, w2); fma2(acc[1][3], qa.y, w3);
        fma2(acc[2][0], qc.x, w0); fma2(acc[2][1], qc.x, w1);
        fma2(acc[2][2], qc.x, w2); fma2(acc[2][3], qc.x, w3);
        fma2(acc[3][0], qc.y, w0); fma2(acc[3][1], qc.y, w1);
        fma2(acc[3][2], qc.y, w2); fma2(acc[3][3], qc.y, w3);
    }

    float* outp;
    if      (job == 0) outp = g_Q;
    else if (job == 1) outp = g_K;
    else if (job == 2) outp = g_V;
    else               outp = g_EQ[job-3];

    const int gcol0 = ch*64 + cg*4;
    const int h  = gcol0 >> 4;
    const int k0 = gcol0 & 15;
#pragma unroll
    for (int p = 0; p < 4; p++) {
        float2 c0 = up2(acc[p][0]), c1 = up2(acc[p][1]);
        float2 c2 = up2(acc[p][2]), c3 = up2(acc[p][3]);
        int rlo = r0 + rg*8 + 2*p;
        if (rlo < nrows) {
            float* o = outp + ((size_t)h*nrows + rlo)*KDD + k0;
            *(float4*)o = make_float4(c0.x, c1.x, c2.x, c3.x);
        }
        if (rlo + 1 < nrows) {
            float* o = outp + ((size_t)h*nrows + rlo + 1)*KDD + k0;
            *(float4*)o = make_float4(c0.y, c1.y, c2.y, c3.y);
        }
    }
}

// ---------------------------------------------------------------------------
// Attention helpers. K/V row = 16 floats = 4 ulonglong2.
// ---------------------------------------------------------------------------
__device__ __forceinline__ float dotp(const ull* qp,
        ulonglong2 ka, ulonglong2 kb, ulonglong2 kc, ulonglong2 kd) {
    ull p0 = mul2(qp[0], ka.x);
    ull p1 = mul2(qp[1], ka.y);
    fma2(p0, qp[2], kb.x); fma2(p1, qp[3], kb.y);
    fma2(p0, qp[4], kc.x); fma2(p1, qp[5], kc.y);
    fma2(p0, qp[6], kd.x); fma2(p1, qp[7], kd.y);
    float2 s = up2(add2(p0, p1));
    return s.x + s.y;
}

__device__ __forceinline__ void accum(float w, ull* acc, float& l,
        ulonglong2 va, ulonglong2 vb, ulonglong2 vc, ulonglong2 vd) {
    l += w;
    ull wp = pk2(w, w);
    fma2(acc[0], wp, va.x); fma2(acc[1], wp, va.y);
    fma2(acc[2], wp, vb.x); fma2(acc[3], wp, vb.y);
    fma2(acc[4], wp, vc.x); fma2(acc[5], wp, vc.y);
    fma2(acc[6], wp, vd.x); fma2(acc[7], wp, vd.y);
}

__device__ __forceinline__ void attn_key2(const ulonglong2* KsU, const ulonglong2* VsU,
        int j,
        const ull* qp0, bool a0, float& l0, ull* acc0,
        const ull* qp1, bool a1, float& l1, ull* acc1) {
    ulonglong2 ka = KsU[j*4+0], kb = KsU[j*4+1], kc = KsU[j*4+2], kd = KsU[j*4+3];
    float s0 = dotp(qp0, ka, kb, kc, kd);
    float s1 = dotp(qp1, ka, kb, kc, kd);
    float w0 = a0 ? ex2(s0) : 0.f;
    float w1 = a1 ? ex2(s1) : 0.f;
    ulonglong2 va = VsU[j*4+0], vb = VsU[j*4+1], vc = VsU[j*4+2], vd = VsU[j*4+3];
    accum(w0, acc0, l0, va, vb, vc, vd);
    accum(w1, acc1, l1, va, vb, vc, vd);
}

__device__ __forceinline__ void loadq(const float* src, ull* qp) {
    const float4* s4 = (const float4*)src;
#pragma unroll
    for (int t = 0; t < 4; t++) {
        float4 v = s4[t];
        qp[2*t]   = pk2(v.x*SCALE2, v.y*SCALE2);
        qp[2*t+1] = pk2(v.z*SCALE2, v.w*SCALE2);
    }
}

// ---------------------------------------------------------------------------
// Kernel 2: attention split over key QUARTERS.
// grid (HB=128, 2 qchunks, 4 key-quarters), block 128, 2 queries/thread.
// ---------------------------------------------------------------------------
__global__ void __launch_bounds__(128, 4) attn_kernel() {
    extern __shared__ float sm[];
    const ulonglong2* KsU = (const ulonglong2*)sm;        // 126 rows * 4
    const ulonglong2* VsU = KsU + 126*4;

    const int hb  = blockIdx.x;
    const int tid = threadIdx.x;
    const int z   = blockIdx.z;
    const int kstart = (z==0) ? 0 : (z==1) ? 126 : (z==2) ? 251 : 376;
    const int nk     = (z==0) ? 126 : 125;

    {
        const float4* K4 = (const float4*)(g_K + ((size_t)hb*GG + kstart)*KDD);
        const float4* V4 = (const float4*)(g_V + ((size_t)hb*GG + kstart)*KDD);
        float4* Ks4 = (float4*)sm;
        float4* Vs4 = Ks4 + 126*4;
        for (int i = tid; i < nk*4; i += 128) {
            Ks4[i] = K4[i];
            Vs4[i] = V4[i];
        }
    }
    __syncthreads();

    const int base = blockIdx.y * 256;
    const int n0 = base + tid;
    const int n1 = base + 128 + tid;
    const bool v0 = (n0 < GG);
    const bool v1 = (n1 < GG);
    const int nn0 = v0 ? n0 : 0;
    const int nn1 = v1 ? n1 : 0;

    ull qp0[8], qp1[8], acc0[8], acc1[8];
    float l0 = 0.f, l1 = 0.f;
#pragma unroll
    for (int k = 0; k < 8; k++) { acc0[k] = 0ull; acc1[k] = 0ull; }
    loadq(g_Q + ((size_t)hb*GG + nn0)*KDD, qp0);
    loadq(g_Q + ((size_t)hb*GG + nn1)*KDD, qp1);

    for (int j = 0; j < nk; j++)
        attn_key2(KsU, VsU, j, qp0, true, l0, acc0, qp1, true, l1, acc1);

    const bool pk0 = (n0 >= 1) && (n0 <= NPP);
    const bool dl0 = (n0 >= NPP+1) && (n0 < GG);
    const bool ex0 = pk0 || dl0;
    const int  p0  = pk0 ? (n0-1) : (n0-NPP-1);
    const bool pk1 = (n1 >= 1) && (n1 <= NPP);
    const bool dl1 = (n1 >= NPP+1) && (n1 < GG);
    const bool ex1 = pk1 || dl1;
    const int  p1  = pk1 ? (n1-1) : (n1-NPP-1);

    {
        const float* e0src = (z < 2) ? (pk0 ? g_EQ[1] : g_EQ[5]) : (pk0 ? g_EQ[2] : g_EQ[4]);
        const float* e1src = (z < 2) ? (pk1 ? g_EQ[1] : g_EQ[5]) : (pk1 ? g_EQ[2] : g_EQ[4]);
        if (ex0) loadq(e0src + ((size_t)hb*NPP + p0)*KDD, qp0);
        if (ex1) loadq(e1src + ((size_t)hb*NPP + p1)*KDD, qp1);
        const int st = (z == 0) ? 1 : 0;
        for (int j = st; j < st + 125; j++)
            attn_key2(KsU, VsU, j, qp0, ex0, l0, acc0, qp1, ex1, l1, acc1);
    }

    {
        const bool c0 = (z < 2) ? dl0 : pk0;
        const bool c1 = (z < 2) ? dl1 : pk1;
        const float* psrc = (z < 2) ? g_EQ[3] : g_EQ[0];
        if (c0) {
            int keyg = ((z < 2) ? 1 : 251) + p0;
            int loc = keyg - kstart;
            if (loc >= 0 && loc < nk) {
                loadq(psrc + ((size_t)hb*NPP + p0)*KDD, qp0);
                float w = ex2(dotp(qp0, KsU[loc*4+0], KsU[loc*4+1], KsU[loc*4+2], KsU[loc*4+3]));
                accum(w, acc0, l0, VsU[loc*4+0], VsU[loc*4+1], VsU[loc*4+2], VsU[loc*4+3]);
            }
        }
        if (c1) {
            int keyg = ((z < 2) ? 1 : 251) + p1;
            int loc = keyg - kstart;
            if (loc >= 0 && loc < nk) {
                loadq(psrc + ((size_t)hb*NPP + p1)*KDD, qp1);
                float w = ex2(dotp(qp1, KsU[loc*4+0], KsU[loc*4+1], KsU[loc*4+2], KsU[loc*4+3]));
                accum(w, acc1, l1, VsU[loc*4+0], VsU[loc*4+1], VsU[loc*4+2], VsU[loc*4+3]);
            }
        }
    }

    if (v0) {
        float4* o = (float4*)(g_pacc[z] + ((size_t)hb*GG + n0)*KDD);
#pragma unroll
        for (int t = 0; t < 4; t++) {
            float2 a0 = up2(acc0[2*t]);
            float2 a1 = up2(acc0[2*t+1]);
            o[t] = make_float4(a0.x, a0.y, a1.x, a1.y);
        }
        g_pl[z][(size_t)hb*GG + n0] = l0;
    }
    if (v1) {
        float4* o = (float4*)(g_pacc[z] + ((size_t)hb*GG + n1)*KDD);
#pragma unroll
        for (int t = 0; t < 4; t++) {
            float2 a0 = up2(acc1[2*t]);
            float2 a1 = up2(acc1[2*t+1]);
            o[t] = make_float4(a0.x, a0.y, a1.x, a1.y);
        }
        g_pl[z][(size_t)hb*GG + n1] = l1;
    }
}

// ---------------------------------------------------------------------------
// Kernel 3: combine 4 partials + normalize + output projection.
// grid 126 (64-token tiles), block 256. Thread: 4 tokens x 8 e-cols.
// No E split -> each partial read exactly once per tile; coalesced combine.
// ---------------------------------------------------------------------------
__global__ void __launch_bounds__(256, 2) out_kernel(const float* __restrict__ Wout,
                                                     float* __restrict__ out) {
    extern __shared__ float sm[];
    float* hs   = sm;                    // 64 * 132
    float* ws   = sm + 64*132;           // 128 * 128
    float* sinv = ws + 128*128;          // 64 * 8

    const int tid = threadIdx.x;
    const int t0  = blockIdx.x * 64;

    // ws: full Wout, straight float4 copy
    {
        const float4* W4 = (const float4*)Wout;
        float4* ws4 = (float4*)ws;
        for (int i = tid; i < 128*32; i += 256) ws4[i] = W4[i];
    }
    // sinv: t fastest for coalesced g_pl reads
    for (int i = tid; i < 64*8; i += 256) {
        int t = i & 63, h = i >> 6;
        int tt = t0 + t;
        float l = 1.f;
        if (tt < NTOK) {
            size_t idx = (size_t)h*NTOK + tt;
            l = (g_pl[0][idx] + g_pl[1][idx]) + (g_pl[2][idx] + g_pl[3][idx]);
        }
        sinv[t*8 + h] = 1.0f / l;
    }
    __syncthreads();

    // hs combine: h outer; tid -> (t, k4) so each partial read is a
    // contiguous 64-token x 4-float4 run (fully coalesced).
    {
        const int t  = tid >> 2;     // 0..63
        const int k4 = tid & 3;      // 0..3
        const int tt = t0 + t;
#pragma unroll
        for (int h = 0; h < 8; h++) {
            float4 v = make_float4(0.f, 0.f, 0.f, 0.f);
            if (tt < NTOK) {
                size_t idx4 = (((size_t)h*NTOK + tt) << 2) + k4;   // float4 index
                float4 a = ((const float4*)g_pacc[0])[idx4];
                float4 b = ((const float4*)g_pacc[1])[idx4];
                float4 c = ((const float4*)g_pacc[2])[idx4];
                float4 d = ((const float4*)g_pacc[3])[idx4];
                float s = sinv[t*8 + h];
                v = make_float4(((a.x+b.x)+(c.x+d.x))*s, ((a.y+b.y)+(c.y+d.y))*s,
                                ((a.z+b.z)+(c.z+d.z))*s, ((a.w+b.w)+(c.w+d.w))*s);
            }
            *(float4*)(hs + t*132 + h*16 + k4*4) = v;
        }
    }
    __syncthreads();

    const int eg = tid & 15;         // cols eg*8 .. +7
    const int tg = tid >> 4;         // 16 groups of 4 tokens
    const ulonglong2* wsU = (const ulonglong2*)ws;   // 32 per hk-row

    ull acc[4][4];
#pragma unroll
    for (int ti = 0; ti < 4; ti++)
#pragma unroll
        for (int c = 0; c < 4; c++) acc[ti][c] = 0ull;

#pragma unroll 4
    for (int hk = 0; hk < 128; hk++) {
        ulonglong2 wa = wsU[hk*32 + eg*2];
        ulonglong2 wb = wsU[hk*32 + eg*2 + 1];
        ull hb[4];
#pragma unroll
        for (int ti = 0; ti < 4; ti++) {
            float hv = hs[(tg*4 + ti)*132 + hk];
            hb[ti] = pk2(hv, hv);
        }
#pragma unroll
        for (int ti = 0; ti < 4; ti++) {
            fma2(acc[ti][0], hb[ti], wa.x);
            fma2(acc[ti][1], hb[ti], wa.y);
            fma2(acc[ti][2], hb[ti], wb.x);
            fma2(acc[ti][3], hb[ti], wb.y);
        }
    }

#pragma unroll
    for (int ti = 0; ti < 4; ti++) {
        int tt = t0 + tg*4 + ti;
        if (tt < NTOK) {
            float2 a0 = up2(acc[ti][0]), a1 = up2(acc[ti][1]);
            float2 a2 = up2(acc[ti][2]), a3 = up2(acc[ti][3]);
            float* o = out + (size_t)tt*EE + eg*8;
            *(float4*)(o)     = make_float4(a0.x, a0.y, a1.x, a1.y);
            *(float4*)(o + 4) = make_float4(a2.x, a2.y, a3.x, a3.y);
        }
    }
}

// ---------------------------------------------------------------------------
extern "C" void kernel_launch(void* const* d_in, const int* in_sizes, int n_in,
                              void* d_out, int out_size) {
    const float* q = (const float*)d_in[0];
    WArgs wa;
    for (int i = 0; i < 9; i++) wa.w[i] = (const float*)d_in[1 + i];
    const float* Wout = (const float*)d_in[10];
    float* out = (float*)d_out;

    const int projSmem = (128*128 + 128*64) * sizeof(float);     // 98304 B
    const int attnSmem = 126*KDD*2*sizeof(float);                // 16128 B
    const int outSmem  = (64*132 + 128*128 + 64*8) * sizeof(float); // 101376 B
    cudaFuncSetAttribute(proj_kernel, cudaFuncAttributeMaxDynamicSharedMemorySize, projSmem);
    cudaFuncSetAttribute(attn_kernel, cudaFuncAttributeMaxDynamicSharedMemorySize, attnSmem);
    cudaFuncSetAttribute(out_kernel,  cudaFuncAttributeMaxDynamicSharedMemorySize, outSmem);

    transpose_kernel<<<dim3((NTOK + 31)/32, 4), dim3(32, 8)>>>(q);
    proj_kernel<<<dim3(381, 2), 256, projSmem>>>(wa);
    attn_kernel<<<dim3(HH*BB, 2, 4), 128, attnSmem>>>();
    out_kernel<<<(NTOK + 63)/64, 256, outSmem>>>(Wout, out);
}